// round 6
// baseline (speedup 1.0000x reference)
#include <cuda_runtime.h>
#include <cuda_bf16.h>
#include <math_constants.h>

#define ROW    131     // 3 coords + 128 features
#define DIMF   128
#define KNN    8
#define MAXSLOTS 12    // supports cnt up to 384 (actual max ~256+5sigma)
#define EPSW   1e-16f
#define NBATCH 1024
#define NMAX   32768
#define INFKEY 0x7F800000u

__device__ double   g_acc;
__device__ unsigned g_done = 0;           // self-resetting via atomicInc wrap
__device__ int      g_bstart[NBATCH + 1];
__device__ float4   g_c1[NMAX];           // packed coords (x,y,z,0)

__device__ __forceinline__ unsigned redux_min_u32(unsigned v) {
    unsigned r;
    asm("redux.sync.min.u32 %0, %1, 0xffffffff;" : "=r"(r) : "r"(v));
    return r;
}

// Prep: zero accumulator, batch-start table by boundary detection, float4 coord repack.
__global__ __launch_bounds__(256) void prep_kernel(
    const float* __restrict__ x1, const int* __restrict__ b1, int n)
{
    const int t = blockIdx.x * blockDim.x + threadIdx.x;
    if (t == 0) g_acc = 0.0;

    if (t < n) {
        const float* xr = x1 + (size_t)t * ROW;
        g_c1[t] = make_float4(xr[0], xr[1], xr[2], 0.0f);

        const int bt = b1[t];
        const int bp = (t == 0) ? -1 : b1[t - 1];
        for (int v = bp + 1; v <= bt; v++) g_bstart[v] = t;
    }
    if (t <= NBATCH) {
        const int blast = b1[n - 1];
        if (t > blast) g_bstart[t] = n;
    }
}

// Core: distances -> packed keys -> 8 fused select+gather rounds -> per-lane sq-error.
template<int NS>
__device__ __forceinline__ float query_core(
    const float* __restrict__ x1, const float* __restrict__ f2,
    int start, int cnt, float cx, float cy, float cz, int lane)
{
    const float n2q = cx*cx + cy*cy + cz*cz;

    unsigned keys[NS];
    #pragma unroll
    for (int s = 0; s < NS; s++) {
        const int j = lane + 32 * s;
        float d2 = CUDART_INF_F;
        if (j < cnt) {
            const float4 a = g_c1[start + j];
            d2 = n2q + (a.x*a.x + a.y*a.y + a.z*a.z)
                     - 2.0f*(cx*a.x + cy*a.y + cz*a.z);
            d2 = fmaxf(d2, 0.0f);
        }
        // d2 >= 0 -> bit pattern order-monotone; round to 14 mantissa bits,
        // embed index in low 9 bits => keys distinct, exact tie-break by index.
        keys[s] = ((__float_as_uint(d2) + 0x100u) & 0xFFFFFE00u) | (unsigned)j;
    }

    float wsum = 0.0f;
    float o0 = 0.f, o1 = 0.f, o2 = 0.f, o3 = 0.f;
    unsigned base = 0;   // keys[] kept biased; true key = keys[s] + base
    #pragma unroll
    for (int k = 0; k < KNN; k++) {
        unsigned m = 0xFFFFFFFFu;
        #pragma unroll
        for (int s = 0; s < NS; s++)
            m = min(m, keys[s]);            // pure IMNMX chain
        m = redux_min_u32(m);
        const unsigned wk = m + base;       // winner true key, all lanes agree

        const unsigned step = m + 1u;       // winner wraps to 0xFFFFFFFF next round
        #pragma unroll
        for (int s = 0; s < NS; s++)
            keys[s] -= step;
        base += step;

        float wv; int g;
        if (wk < INFKEY) {
            wv = 1.0f / fmaxf(__uint_as_float(wk & 0xFFFFFE00u), EPSW);
            g  = start + (int)(wk & 0x1FFu);
        } else {
            wv = 0.0f;   // cnt < K padding: matches reference (w = 1/inf = 0)
            g  = start;
        }
        wsum += wv;

        // gather features for this neighbor now -> load latency overlaps later rounds
        const float* fr = x1 + (size_t)g * ROW + 3;
        o0 += wv * fr[lane];
        o1 += wv * fr[lane + 32];
        o2 += wv * fr[lane + 64];
        o3 += wv * fr[lane + 96];
    }

    const float inv = 1.0f / wsum;
    const float d0 = o0 * inv - f2[lane];
    const float d1 = o1 * inv - f2[lane + 32];
    const float d2_ = o2 * inv - f2[lane + 64];
    const float d3 = o3 * inv - f2[lane + 96];
    return d0*d0 + d1*d1 + d2_*d2_ + d3*d3;
}

__global__ __launch_bounds__(256) void knn_mse_kernel(
    const float* __restrict__ x1,
    const float* __restrict__ x2,
    const int*   __restrict__ b2,
    float*       __restrict__ out,
    int n)
{
    __shared__ float red[8];

    const int tid  = threadIdx.x;
    const int lane = tid & 31;
    const int wid  = tid >> 5;
    const int q    = blockIdx.x * 8 + wid;

    const float* xq = x2 + (size_t)q * ROW;
    const float cx = xq[0], cy = xq[1], cz = xq[2];
    const int b = min(max(b2[q], 0), NBATCH - 1);

    const int start = g_bstart[b];
    const int end   = g_bstart[b + 1];
    int cnt = end - start;
    if (cnt > MAXSLOTS * 32) cnt = MAXSLOTS * 32;   // safety clamp; never fires

    float acc;
    if (cnt <= 9 * 32)
        acc = query_core<9>(x1, xq + 3, start, cnt, cx, cy, cz, lane);
    else
        acc = query_core<MAXSLOTS>(x1, xq + 3, start, cnt, cx, cy, cz, lane);

    // ---- warp reduce -> shared -> one atomic per block; last block finalizes ----
    #pragma unroll
    for (int offr = 16; offr; offr >>= 1)
        acc += __shfl_down_sync(0xffffffffu, acc, offr);
    if (lane == 0) red[wid] = acc;
    __syncthreads();
    if (tid == 0) {
        float s = 0.f;
        #pragma unroll
        for (int i = 0; i < 8; i++) s += red[i];
        atomicAdd(&g_acc, (double)s);
        __threadfence();
        const unsigned rank = atomicInc(&g_done, gridDim.x - 1);  // wraps -> self-reset
        if (rank == gridDim.x - 1) {
            out[0] = (float)(g_acc / ((double)n * (double)DIMF));
        }
    }
}

extern "C" void kernel_launch(void* const* d_in, const int* in_sizes, int n_in,
                              void* d_out, int out_size)
{
    const float* x1 = (const float*)d_in[0];
    const float* x2 = (const float*)d_in[1];
    const int*   b1 = (const int*)d_in[2];
    const int*   b2 = (const int*)d_in[3];
    const int n = in_sizes[2];   // N points

    prep_kernel<<<(n + 255) / 256, 256>>>(x1, b1, n);
    knn_mse_kernel<<<n / 8, 256>>>(x1, x2, b2, (float*)d_out, n);
}

// round 7
// speedup vs baseline: 1.0908x; 1.0908x over previous
#include <cuda_runtime.h>
#include <cuda_bf16.h>
#include <math_constants.h>

#define ROW    131     // 3 coords + 128 features
#define DIMF   128
#define KNN    8
#define SLOTS  12      // cnt up to 384 (actual max ~256+5sigma)
#define EPSW   1e-16f
#define NBATCH 1024
#define NMAX   32768
#define INFKEY 0x7F800000u

__device__ double   g_acc;
__device__ unsigned g_done = 0;           // self-resetting via atomicInc wrap
__device__ int      g_bstart[NBATCH + 1];
__device__ float4   g_c1[NMAX];           // packed coords (x,y,z,0)

__device__ __forceinline__ unsigned redux_min_u32(unsigned v) {
    unsigned r;
    asm("redux.sync.min.u32 %0, %1, 0xffffffff;" : "=r"(r) : "r"(v));
    return r;
}

// Prep: zero accumulator, batch-start table by boundary detection, float4 coord repack.
__global__ __launch_bounds__(256) void prep_kernel(
    const float* __restrict__ x1, const int* __restrict__ b1, int n)
{
    const int t = blockIdx.x * blockDim.x + threadIdx.x;
    if (t == 0) g_acc = 0.0;

    if (t < n) {
        const float* xr = x1 + (size_t)t * ROW;
        g_c1[t] = make_float4(xr[0], xr[1], xr[2], 0.0f);

        const int bt = b1[t];
        const int bp = (t == 0) ? -1 : b1[t - 1];
        for (int v = bp + 1; v <= bt; v++) g_bstart[v] = t;
    }
    if (t <= NBATCH) {
        const int blast = b1[n - 1];
        if (t > blast) g_bstart[t] = n;
    }
}

__global__ __launch_bounds__(128) void knn_mse_kernel(
    const float* __restrict__ x1,
    const float* __restrict__ x2,
    const int*   __restrict__ b2,
    float*       __restrict__ out,
    int n)
{
    __shared__ float red[4];

    const int tid  = threadIdx.x;
    const int lane = tid & 31;
    const int wid  = tid >> 5;
    const int q    = blockIdx.x * 4 + wid;

    const float* xq = x2 + (size_t)q * ROW;
    const float cx = xq[0], cy = xq[1], cz = xq[2];
    const int b = min(max(b2[q], 0), NBATCH - 1);

    // preload this query's features early: latency overlaps distance+selection
    const float* f2 = xq + 3;
    const float t0 = f2[lane], t1 = f2[lane + 32], t2 = f2[lane + 64], t3 = f2[lane + 96];

    const int start = g_bstart[b];
    const int end   = g_bstart[b + 1];
    int cnt = end - start;
    if (cnt > SLOTS * 32) cnt = SLOTS * 32;   // safety clamp; never fires

    // ---- distance phase -> packed keys: rounded d2 bits (high 23) | j (low 9) ----
    const float n2q = cx*cx + cy*cy + cz*cz;
    unsigned keys[SLOTS];
    #pragma unroll
    for (int s = 0; s < SLOTS; s++) {
        const int j = lane + 32 * s;
        float d2 = CUDART_INF_F;
        if (j < cnt) {
            const float4 a = g_c1[start + j];
            d2 = n2q + (a.x*a.x + a.y*a.y + a.z*a.z)
                     - 2.0f*(cx*a.x + cy*a.y + cz*a.z);
            d2 = fmaxf(d2, 0.0f);
        }
        // d2 >= 0 -> order-monotone bits; round to 14 mantissa bits, embed index:
        // keys distinct, exact tie-break by lowest index.
        keys[s] = ((__float_as_uint(d2) + 0x100u) & 0xFFFFFE00u) | (unsigned)j;
    }

    // ---- selection: 8 rounds; tree-min scan + redux; biased keys exclude winners ----
    float w[KNN];
    int   gi[KNN];
    unsigned base = 0;   // true key = keys[s] + base
    #pragma unroll
    for (int k = 0; k < KNN; k++) {
        // pairwise tree min (dep depth 4) instead of serial 12-chain
        unsigned m01 = min(keys[0], keys[1]),  m23 = min(keys[2],  keys[3]);
        unsigned m45 = min(keys[4], keys[5]),  m67 = min(keys[6],  keys[7]);
        unsigned m89 = min(keys[8], keys[9]),  mAB = min(keys[10], keys[11]);
        unsigned m0  = min(m01, m23), m1 = min(m45, m67), m2 = min(m89, mAB);
        unsigned m   = min(min(m0, m1), m2);
        m = redux_min_u32(m);
        const unsigned wk = m + base;        // winner true key, all lanes agree

        const unsigned step = m + 1u;        // winner wraps to 0xFFFFFFFF next round
        #pragma unroll
        for (int s = 0; s < SLOTS; s++)
            keys[s] -= step;
        base += step;

        if (wk < INFKEY) {
            w[k]  = 1.0f / fmaxf(__uint_as_float(wk & 0xFFFFFE00u), EPSW);
            gi[k] = start + (int)(wk & 0x1FFu);
        } else {
            w[k]  = 0.0f;   // cnt < K padding: matches reference (w = 1/inf = 0)
            gi[k] = start;
        }
    }

    // ---- gather phase: all 32 loads batched (high MLP), then FMAs ----
    float wsum = 0.0f;
    #pragma unroll
    for (int k = 0; k < KNN; k++) wsum += w[k];

    float o0 = 0.f, o1 = 0.f, o2 = 0.f, o3 = 0.f;
    #pragma unroll
    for (int k = 0; k < KNN; k++) {
        const float* fr = x1 + (size_t)gi[k] * ROW + 3;
        const float wk = w[k];
        o0 += wk * fr[lane];
        o1 += wk * fr[lane + 32];
        o2 += wk * fr[lane + 64];
        o3 += wk * fr[lane + 96];
    }

    const float inv = 1.0f / wsum;
    const float d0 = o0 * inv - t0;
    const float d1 = o1 * inv - t1;
    const float d2_ = o2 * inv - t2;
    const float d3 = o3 * inv - t3;
    float acc = d0*d0 + d1*d1 + d2_*d2_ + d3*d3;

    // ---- warp reduce -> shared -> one atomic per block; last block finalizes ----
    #pragma unroll
    for (int offr = 16; offr; offr >>= 1)
        acc += __shfl_down_sync(0xffffffffu, acc, offr);
    if (lane == 0) red[wid] = acc;
    __syncthreads();
    if (tid == 0) {
        float s = red[0] + red[1] + red[2] + red[3];
        atomicAdd(&g_acc, (double)s);
        __threadfence();
        const unsigned rank = atomicInc(&g_done, gridDim.x - 1);  // wraps -> self-reset
        if (rank == gridDim.x - 1) {
            out[0] = (float)(g_acc / ((double)n * (double)DIMF));
        }
    }
}

extern "C" void kernel_launch(void* const* d_in, const int* in_sizes, int n_in,
                              void* d_out, int out_size)
{
    const float* x1 = (const float*)d_in[0];
    const float* x2 = (const float*)d_in[1];
    const int*   b1 = (const int*)d_in[2];
    const int*   b2 = (const int*)d_in[3];
    const int n = in_sizes[2];   // N points

    prep_kernel<<<(n + 255) / 256, 256>>>(x1, b1, n);
    knn_mse_kernel<<<n / 4, 128>>>(x1, x2, b2, (float*)d_out, n);
}

// round 8
// speedup vs baseline: 1.0923x; 1.0014x over previous
#include <cuda_runtime.h>
#include <cuda_bf16.h>
#include <math_constants.h>

#define ROW    131     // 3 coords + 128 features
#define DIMF   128
#define KNN    8
#define MAXSLOTS 12    // cnt up to 384 (actual max ~256+5sigma)
#define EPSW   1e-16f
#define NBATCH 1024
#define NMAX   32768
#define INFKEY 0x7F800000u

__device__ double   g_acc;
__device__ unsigned g_done = 0;           // self-resetting via atomicInc wrap
__device__ int      g_bstart[NBATCH + 1];
__device__ float4   g_c1[NMAX];           // (x, y, z, |c|^2)

__device__ __forceinline__ unsigned redux_min_u32(unsigned v) {
    unsigned r;
    asm("redux.sync.min.u32 %0, %1, 0xffffffff;" : "=r"(r) : "r"(v));
    return r;
}

// Prep: zero accumulator, batch-start table by boundary detection,
// float4 coord repack with precomputed squared norm in .w.
__global__ __launch_bounds__(256) void prep_kernel(
    const float* __restrict__ x1, const int* __restrict__ b1, int n)
{
    const int t = blockIdx.x * blockDim.x + threadIdx.x;
    if (t == 0) g_acc = 0.0;

    if (t < n) {
        const float* xr = x1 + (size_t)t * ROW;
        const float ax = xr[0], ay = xr[1], az = xr[2];
        g_c1[t] = make_float4(ax, ay, az, ax*ax + ay*ay + az*az);

        const int bt = b1[t];
        const int bp = (t == 0) ? -1 : b1[t - 1];
        for (int v = bp + 1; v <= bt; v++) g_bstart[v] = t;
    }
    if (t <= NBATCH) {
        const int blast = b1[n - 1];
        if (t > blast) g_bstart[t] = n;
    }
}

template<int NS>
__device__ __forceinline__ float query_core(
    const float* __restrict__ x1, const float* __restrict__ f2,
    int start, int cnt, float cx, float cy, float cz, int lane)
{
    const float n2q = cx*cx + cy*cy + cz*cz;
    const float m2x = -2.0f*cx, m2y = -2.0f*cy, m2z = -2.0f*cz;

    // ---- distance phase -> packed keys: rounded d2 bits (high 23) | j (low 9) ----
    unsigned keys[NS];
    #pragma unroll
    for (int s = 0; s < NS; s++) {
        const int j = lane + 32 * s;
        float d2 = CUDART_INF_F;
        if (j < cnt) {
            const float4 a = g_c1[start + j];
            float t = fmaf(a.x, m2x, a.w);    // |a|^2 - 2*dot, 3 FMAs
            t = fmaf(a.y, m2y, t);
            t = fmaf(a.z, m2z, t);
            d2 = fmaxf(t + n2q, 0.0f);
        }
        // d2 >= 0 -> order-monotone bits; round to 14 mantissa bits, embed index:
        // keys distinct, exact tie-break by lowest index.
        keys[s] = ((__float_as_uint(d2) + 0x100u) & 0xFFFFFE00u) | (unsigned)j;
    }

    // ---- selection: 8 rounds of (tree-min scan -> redux -> rebias); store packed winners ----
    unsigned wks[KNN];
    unsigned base = 0;   // true key = keys[s] + base
    #pragma unroll
    for (int k = 0; k < KNN; k++) {
        unsigned m;
        if (NS == 9) {
            const unsigned a = min(min(keys[0], keys[1]), min(keys[2], keys[3]));
            const unsigned b = min(min(keys[4], keys[5]), min(keys[6], keys[7]));
            m = min(min(a, b), keys[8]);
        } else {
            const unsigned m01 = min(keys[0], keys[1]),  m23 = min(keys[2],  keys[3]);
            const unsigned m45 = min(keys[4], keys[5]),  m67 = min(keys[6],  keys[7]);
            const unsigned m89 = min(keys[8], keys[9]),  mAB = min(keys[NS-2], keys[NS-1]);
            m = min(min(min(m01, m23), min(m45, m67)), min(m89, mAB));
        }
        m = redux_min_u32(m);
        wks[k] = m + base;                   // winner true key, all lanes agree

        const unsigned step = m + 1u;        // winner wraps to 0xFFFFFFFF next round
        #pragma unroll
        for (int s = 0; s < NS; s++)
            keys[s] -= step;
        base += step;
    }

    // ---- gather phase: decode winners, 32 batched loads, weighted FMAs ----
    float wsum = 0.0f;
    float o0 = 0.f, o1 = 0.f, o2 = 0.f, o3 = 0.f;
    #pragma unroll
    for (int k = 0; k < KNN; k++) {
        const unsigned wk = wks[k];
        const bool valid = wk < INFKEY;
        const float d2r = __uint_as_float(wk & 0xFFFFFE00u);
        const float wv = valid ? (1.0f / fmaxf(d2r, EPSW)) : 0.0f;  // cnt<K pad: w=0
        const int g = valid ? (start + (int)(wk & 0x1FFu)) : start;
        wsum += wv;

        const float* fr = x1 + (size_t)g * ROW + 3;
        o0 += wv * fr[lane];
        o1 += wv * fr[lane + 32];
        o2 += wv * fr[lane + 64];
        o3 += wv * fr[lane + 96];
    }

    const float inv = 1.0f / wsum;
    const float d0 = o0 * inv - f2[lane];
    const float d1 = o1 * inv - f2[lane + 32];
    const float d2_ = o2 * inv - f2[lane + 64];
    const float d3 = o3 * inv - f2[lane + 96];
    return d0*d0 + d1*d1 + d2_*d2_ + d3*d3;
}

__global__ __launch_bounds__(128) void knn_mse_kernel(
    const float* __restrict__ x1,
    const float* __restrict__ x2,
    const int*   __restrict__ b2,
    float*       __restrict__ out,
    int n)
{
    __shared__ float red[4];

    const int tid  = threadIdx.x;
    const int lane = tid & 31;
    const int wid  = tid >> 5;
    const int q    = blockIdx.x * 4 + wid;

    const float* xq = x2 + (size_t)q * ROW;
    const float cx = xq[0], cy = xq[1], cz = xq[2];
    const int b = min(max(b2[q], 0), NBATCH - 1);

    const int start = g_bstart[b];
    const int end   = g_bstart[b + 1];
    int cnt = end - start;
    if (cnt > MAXSLOTS * 32) cnt = MAXSLOTS * 32;   // safety clamp; never fires

    float acc;
    if (cnt <= 9 * 32)
        acc = query_core<9>(x1, xq + 3, start, cnt, cx, cy, cz, lane);
    else
        acc = query_core<MAXSLOTS>(x1, xq + 3, start, cnt, cx, cy, cz, lane);

    // ---- warp reduce -> shared -> one atomic per block; last block finalizes ----
    #pragma unroll
    for (int offr = 16; offr; offr >>= 1)
        acc += __shfl_down_sync(0xffffffffu, acc, offr);
    if (lane == 0) red[wid] = acc;
    __syncthreads();
    if (tid == 0) {
        float s = red[0] + red[1] + red[2] + red[3];
        atomicAdd(&g_acc, (double)s);
        __threadfence();
        const unsigned rank = atomicInc(&g_done, gridDim.x - 1);  // wraps -> self-reset
        if (rank == gridDim.x - 1) {
            out[0] = (float)(g_acc / ((double)n * (double)DIMF));
        }
    }
}

extern "C" void kernel_launch(void* const* d_in, const int* in_sizes, int n_in,
                              void* d_out, int out_size)
{
    const float* x1 = (const float*)d_in[0];
    const float* x2 = (const float*)d_in[1];
    const int*   b1 = (const int*)d_in[2];
    const int*   b2 = (const int*)d_in[3];
    const int n = in_sizes[2];   // N points

    prep_kernel<<<(n + 255) / 256, 256>>>(x1, b1, n);
    knn_mse_kernel<<<n / 4, 128>>>(x1, x2, b2, (float*)d_out, n);
}